// round 2
// baseline (speedup 1.0000x reference)
#include <cuda_runtime.h>
#include <cstdint>

// Problem constants
#define BB 128
#define TT 512
#define DD 512
#define HH 512
#define G4 2048            // 4*H
#define MX (BB*TT)         // 65536 rows of the input-projection GEMM

// Device scratch (allocation-free requirement: __device__ globals)
__device__ float g_pre[(size_t)MX * G4];     // 512 MB: x@Wx + b, permuted cols, row m=b*T+t
__device__ float g_Wxp[DD * G4];             // permuted input weights
__device__ float g_Whp[HH * G4];             // permuted recurrent weights
__device__ float g_bp[G4];                   // permuted bias
__device__ float g_h[2][BB * HH];            // ping-pong hidden state

__device__ __forceinline__ uint32_t f2tf32(float f) {
    uint32_t u;
    asm("cvt.rna.tf32.f32 %0, %1;" : "=r"(u) : "f"(f));
    return u;
}

__device__ __forceinline__ void mma8(float d[4], const uint32_t a[4], const uint32_t b[2]) {
    asm volatile(
        "mma.sync.aligned.m16n8k8.row.col.f32.tf32.tf32.f32 "
        "{%0,%1,%2,%3}, {%4,%5,%6,%7}, {%8,%9}, {%0,%1,%2,%3};"
        : "+f"(d[0]), "+f"(d[1]), "+f"(d[2]), "+f"(d[3])
        : "r"(a[0]), "r"(a[1]), "r"(a[2]), "r"(a[3]), "r"(b[0]), "r"(b[1]));
}

// ---------------------------------------------------------------------------
// Shared GEMM core: C[128 x 64] tile, K=512, A row-major lda=512 (fp32),
// B row-major ldb=2048 (fp32), tf32 MMA. 256 threads = 8 warps, warp tile 32x32.
// ---------------------------------------------------------------------------
__device__ __forceinline__ void gemm_tile_512(
    const float* __restrict__ A, const float* __restrict__ Bmat,
    int m0, int n0,
    uint32_t (*As)[33], uint32_t (*Bs)[65],
    float acc[2][4][4])
{
    const int tid = threadIdx.x;
    const int lane = tid & 31;
    const int warp = tid >> 5;
    const int wm = warp >> 1;   // 0..3
    const int wn = warp & 1;    // 0..1

    for (int k0 = 0; k0 < 512; k0 += 32) {
        // Load A tile [128 x 32]: 2 threads per row, 16 floats each
        {
            int r = tid >> 1;
            int c = (tid & 1) * 16;
            const float* srcA = A + (size_t)(m0 + r) * 512 + k0 + c;
            #pragma unroll
            for (int i = 0; i < 4; i++) {
                float4 v = *(const float4*)(srcA + 4 * i);
                As[r][c + 4*i + 0] = f2tf32(v.x);
                As[r][c + 4*i + 1] = f2tf32(v.y);
                As[r][c + 4*i + 2] = f2tf32(v.z);
                As[r][c + 4*i + 3] = f2tf32(v.w);
            }
        }
        // Load B tile [32 x 64]: 8 threads per row, 8 floats each
        {
            int r = tid >> 3;
            int c = (tid & 7) * 8;
            const float* srcB = Bmat + (size_t)(k0 + r) * 2048 + n0 + c;
            #pragma unroll
            for (int i = 0; i < 2; i++) {
                float4 v = *(const float4*)(srcB + 4 * i);
                Bs[r][c + 4*i + 0] = f2tf32(v.x);
                Bs[r][c + 4*i + 1] = f2tf32(v.y);
                Bs[r][c + 4*i + 2] = f2tf32(v.z);
                Bs[r][c + 4*i + 3] = f2tf32(v.w);
            }
        }
        __syncthreads();

        #pragma unroll
        for (int ks = 0; ks < 4; ks++) {
            uint32_t a[2][4], bb[4][2];
            const int kk = ks * 8 + (lane & 3);
            #pragma unroll
            for (int s = 0; s < 2; s++) {
                int rr = wm * 32 + s * 16 + (lane >> 2);
                a[s][0] = As[rr][kk];
                a[s][1] = As[rr + 8][kk];
                a[s][2] = As[rr][kk + 4];
                a[s][3] = As[rr + 8][kk + 4];
            }
            #pragma unroll
            for (int u = 0; u < 4; u++) {
                int cc = wn * 32 + u * 8 + (lane >> 2);
                bb[u][0] = Bs[kk][cc];
                bb[u][1] = Bs[kk + 4][cc];
            }
            #pragma unroll
            for (int s = 0; s < 2; s++)
                #pragma unroll
                for (int u = 0; u < 4; u++)
                    mma8(acc[s][u], a[s], bb[u]);
        }
        __syncthreads();
    }
}

// ---------------------------------------------------------------------------
// Kernel 0: permute W (gate-blocked cols -> interleaved col' = 4*h + g), split
// into Wx (rows 0..511) and Wh (rows 512..1023); permute bias.
// ---------------------------------------------------------------------------
__global__ void permute_W_kernel(const float* __restrict__ W, const float* __restrict__ bias) {
    int idx = blockIdx.x * 256 + threadIdx.x;
    if (idx < 1024 * 2048) {
        int d = idx >> 11;
        int col = idx & 2047;
        int g = col >> 9;
        int h = col & 511;
        int colp = 4 * h + g;
        float v = W[idx];
        if (d < 512) g_Wxp[d * 2048 + colp] = v;
        else         g_Whp[(d - 512) * 2048 + colp] = v;
    }
    if (idx < 2048) {
        int g = idx >> 9;
        int h = idx & 511;
        g_bp[4 * h + g] = bias[idx];
    }
}

// ---------------------------------------------------------------------------
// Kernel 1: input projection. A = word_vectors viewed as [65536 x 512]
// (row m = b*T + t). C = g_pre[m][col'] = A @ Wxp + bias_p.
// Grid: (32 n-tiles, 512 m-tiles), 256 threads.
// ---------------------------------------------------------------------------
__global__ void __launch_bounds__(256) gemm_x_kernel(const float* __restrict__ X) {
    __shared__ uint32_t As[128][33];
    __shared__ uint32_t Bs[32][65];
    const int n0 = blockIdx.x * 64;
    const int m0 = blockIdx.y * 128;
    const int lane = threadIdx.x & 31;
    const int warp = threadIdx.x >> 5;
    const int wm = warp >> 1, wn = warp & 1;

    float acc[2][4][4];
    #pragma unroll
    for (int s = 0; s < 2; s++)
        #pragma unroll
        for (int u = 0; u < 4; u++)
            #pragma unroll
            for (int i = 0; i < 4; i++) acc[s][u][i] = 0.f;

    gemm_tile_512(X, g_Wxp, m0, n0, As, Bs, acc);

    #pragma unroll
    for (int s = 0; s < 2; s++) {
        int row = m0 + wm * 32 + s * 16 + (lane >> 2);
        #pragma unroll
        for (int u = 0; u < 4; u++) {
            int col = n0 + wn * 32 + u * 8 + 2 * (lane & 3);
            size_t base = (size_t)row * 2048 + col;
            g_pre[base]                   = acc[s][u][0] + g_bp[col];
            g_pre[base + 1]               = acc[s][u][1] + g_bp[col + 1];
            g_pre[base + (size_t)8*2048]     = acc[s][u][2] + g_bp[col];
            g_pre[base + (size_t)8*2048 + 1] = acc[s][u][3] + g_bp[col + 1];
        }
    }
}

// ---------------------------------------------------------------------------
// Kernel 2: init state. c lives in d_out's final_c region; h in g_h[0].
// ---------------------------------------------------------------------------
__global__ void init_state_kernel(const float* __restrict__ ic, const float* __restrict__ ih,
                                  float* __restrict__ c_state) {
    int i = blockIdx.x * 256 + threadIdx.x;
    if (i < BB * HH) {
        c_state[i] = ic[i];
        g_h[0][i] = ih[i];
    }
}

// ---------------------------------------------------------------------------
// Kernel 3: one LSTM step. z = g_pre[.,t,.] + h_in @ Whp; fused gates.
// Grid: 32 CTAs, each owns cols' [n0, n0+64) == h-cols [n0/4, n0/4+16).
// h ping-pong: read g_h[t&1], write g_h[(t&1)^1]. c updated in place.
// ---------------------------------------------------------------------------
__global__ void __launch_bounds__(256) lstm_step_kernel(
    int t, const int* __restrict__ num_words,
    float* __restrict__ c_state, float* __restrict__ out)
{
    __shared__ __align__(16) unsigned char smemb[34816]; // union: (As+Bs)=25216 | zs=34816
    uint32_t (*As)[33] = (uint32_t(*)[33])smemb;
    uint32_t (*Bs)[65] = (uint32_t(*)[65])(smemb + 128 * 33 * 4);
    float (*zs)[68] = (float(*)[68])smemb;

    const float* __restrict__ h_in = g_h[t & 1];
    float* __restrict__ h_out = g_h[(t & 1) ^ 1];

    const int n0 = blockIdx.x * 64;
    const int tid = threadIdx.x;
    const int lane = tid & 31;
    const int warp = tid >> 5;
    const int wm = warp >> 1, wn = warp & 1;

    float acc[2][4][4];
    #pragma unroll
    for (int s = 0; s < 2; s++)
        #pragma unroll
        for (int u = 0; u < 4; u++)
            #pragma unroll
            for (int i = 0; i < 4; i++) acc[s][u][i] = 0.f;

    gemm_tile_512(h_in, g_Whp, 0, n0, As, Bs, acc);

    // Stage z = acc + pre into shared (switch smem use; gemm ended with syncthreads)
    #pragma unroll
    for (int s = 0; s < 2; s++) {
        int row = wm * 32 + s * 16 + (lane >> 2);      // row == batch b
        #pragma unroll
        for (int u = 0; u < 4; u++) {
            int cl = wn * 32 + u * 8 + 2 * (lane & 3); // local col'
            size_t p0 = ((size_t)row * TT + t) * 2048 + n0 + cl;
            size_t p1 = ((size_t)(row + 8) * TT + t) * 2048 + n0 + cl;
            zs[row][cl]         = acc[s][u][0] + g_pre[p0];
            zs[row][cl + 1]     = acc[s][u][1] + g_pre[p0 + 1];
            zs[row + 8][cl]     = acc[s][u][2] + g_pre[p1];
            zs[row + 8][cl + 1] = acc[s][u][3] + g_pre[p1 + 1];
        }
    }
    __syncthreads();

    // Fused gate epilogue: 128 b x 16 h-cols per CTA
    for (int i = tid; i < 128 * 16; i += 256) {
        int b = i >> 4;
        int hl = i & 15;
        float zi = zs[b][4 * hl + 0];
        float zj = zs[b][4 * hl + 1];
        float zf = zs[b][4 * hl + 2];
        float zo = zs[b][4 * hl + 3];
        int hcol = (n0 >> 2) + hl;
        int sidx = b * HH + hcol;

        float c_old = c_state[sidx];
        float h_old = h_in[sidx];
        float si = 1.f / (1.f + __expf(-zi));
        float sf = 1.f / (1.f + __expf(-(zf + 1.0f)));   // FORGET_BIAS = 1
        float so = 1.f / (1.f + __expf(-zo));
        float tj = tanhf(zj);
        float nc = c_old * sf + si * tj;
        float nh = tanhf(nc) * so;

        bool m = t < num_words[b];
        c_state[sidx] = m ? nc : c_old;
        h_out[sidx]   = m ? nh : h_old;
        out[(size_t)t * (BB * HH) + sidx] = m ? nh : 0.f;
    }
}

// ---------------------------------------------------------------------------
// Kernel 4: copy final h (after 512 steps it sits in g_h[0]) into d_out.
// ---------------------------------------------------------------------------
__global__ void final_h_kernel(float* __restrict__ h_final) {
    int i = blockIdx.x * 256 + threadIdx.x;
    if (i < BB * HH) h_final[i] = g_h[0][i];
}

// ---------------------------------------------------------------------------
extern "C" void kernel_launch(void* const* d_in, const int* in_sizes, int n_in,
                              void* d_out, int out_size) {
    const float* x    = (const float*)d_in[0];  // [B,T,D]
    const int*   nw   = (const int*)  d_in[1];  // [B]
    const float* ic   = (const float*)d_in[2];  // [B,H]
    const float* ih   = (const float*)d_in[3];  // [B,H]
    const float* W    = (const float*)d_in[4];  // [D+H, 4H]
    const float* bias = (const float*)d_in[5];  // [4H]

    float* out = (float*)d_out;
    float* c_state = out + (size_t)TT * BB * HH;      // final_c region, used as live c
    float* h_final = c_state + (size_t)BB * HH;       // final_h region

    permute_W_kernel<<<8192, 256>>>(W, bias);
    gemm_x_kernel<<<dim3(32, 512), 256>>>(x);
    init_state_kernel<<<(BB * HH + 255) / 256, 256>>>(ic, ih, c_state);

    for (int t = 0; t < TT; t++) {
        lstm_step_kernel<<<32, 256>>>(t, nw, c_state, out);
    }

    final_h_kernel<<<(BB * HH + 255) / 256, 256>>>(h_final);
}

// round 3
// speedup vs baseline: 3.6543x; 3.6543x over previous
#include <cuda_runtime.h>
#include <cstdint>

// Problem constants
#define BB 128
#define TT 512
#define DD 512
#define HH 512
#define G4 2048            // 4*H
#define MX (BB*TT)

// Persistent-kernel tiling
#define NCTA 128
#define ROWS 32            // batch rows per CTA
#define NC   64            // permuted cols per CTA (=> 16 h cols)
#define ASTRIDE 524        // word stride, conflict-free frag loads (524 % 32 = 12)
#define BSTRIDE 524
#define ZSTRIDE 68

// Device scratch (allocation-free requirement: __device__ globals)
__device__ float g_pre[(size_t)MX * G4];     // x@Wx + b, permuted cols, row m=b*T+t
__device__ float g_Wxp[DD * G4];
__device__ float g_Whp[HH * G4];
__device__ float g_bp[G4];
__device__ float g_h[2][BB * HH];            // ping-pong hidden state (tf32-rounded bits)
__device__ unsigned g_cnt;                    // grid barrier counter

__device__ __forceinline__ uint32_t f2tf32(float f) {
    uint32_t u;
    asm("cvt.rna.tf32.f32 %0, %1;" : "=r"(u) : "f"(f));
    return u;
}

__device__ __forceinline__ void mma8(float d[4], const uint32_t a[4], const uint32_t b[2]) {
    asm volatile(
        "mma.sync.aligned.m16n8k8.row.col.f32.tf32.tf32.f32 "
        "{%0,%1,%2,%3}, {%4,%5,%6,%7}, {%8,%9}, {%0,%1,%2,%3};"
        : "+f"(d[0]), "+f"(d[1]), "+f"(d[2]), "+f"(d[3])
        : "r"(a[0]), "r"(a[1]), "r"(a[2]), "r"(a[3]), "r"(b[0]), "r"(b[1]));
}

// ---------------------------------------------------------------------------
// Kernel 0: permute W (gate-blocked cols -> interleaved col' = 4*h + g)
// ---------------------------------------------------------------------------
__global__ void permute_W_kernel(const float* __restrict__ W, const float* __restrict__ bias) {
    int idx = blockIdx.x * 256 + threadIdx.x;
    if (idx < 1024 * 2048) {
        int d = idx >> 11;
        int col = idx & 2047;
        int g = col >> 9;
        int h = col & 511;
        int colp = 4 * h + g;
        float v = W[idx];
        if (d < 512) g_Wxp[d * 2048 + colp] = v;
        else         g_Whp[(d - 512) * 2048 + colp] = v;
    }
    if (idx < 2048) {
        int g = idx >> 9;
        int h = idx & 511;
        g_bp[4 * h + g] = bias[idx];
    }
}

// ---------------------------------------------------------------------------
// Kernel 1: input projection GEMM  g_pre = X @ Wxp + b   (X viewed [65536 x 512])
// ---------------------------------------------------------------------------
__global__ void __launch_bounds__(256) gemm_x_kernel(const float* __restrict__ X) {
    __shared__ uint32_t As[128][33];
    __shared__ uint32_t Bs[32][65];
    const int n0 = blockIdx.x * 64;
    const int m0 = blockIdx.y * 128;
    const int tid = threadIdx.x;
    const int lane = tid & 31;
    const int warp = tid >> 5;
    const int wm = warp >> 1, wn = warp & 1;

    float acc[2][4][4];
    #pragma unroll
    for (int s = 0; s < 2; s++)
        #pragma unroll
        for (int u = 0; u < 4; u++)
            #pragma unroll
            for (int i = 0; i < 4; i++) acc[s][u][i] = 0.f;

    for (int k0 = 0; k0 < 512; k0 += 32) {
        {
            int r = tid >> 1;
            int c = (tid & 1) * 16;
            const float* srcA = X + (size_t)(m0 + r) * 512 + k0 + c;
            #pragma unroll
            for (int i = 0; i < 4; i++) {
                float4 v = *(const float4*)(srcA + 4 * i);
                As[r][c + 4*i + 0] = f2tf32(v.x);
                As[r][c + 4*i + 1] = f2tf32(v.y);
                As[r][c + 4*i + 2] = f2tf32(v.z);
                As[r][c + 4*i + 3] = f2tf32(v.w);
            }
        }
        {
            int r = tid >> 3;
            int c = (tid & 7) * 8;
            const float* srcB = g_Wxp + (size_t)(k0 + r) * 2048 + n0 + c;
            #pragma unroll
            for (int i = 0; i < 2; i++) {
                float4 v = *(const float4*)(srcB + 4 * i);
                Bs[r][c + 4*i + 0] = f2tf32(v.x);
                Bs[r][c + 4*i + 1] = f2tf32(v.y);
                Bs[r][c + 4*i + 2] = f2tf32(v.z);
                Bs[r][c + 4*i + 3] = f2tf32(v.w);
            }
        }
        __syncthreads();

        #pragma unroll
        for (int ks = 0; ks < 4; ks++) {
            uint32_t a[2][4], bb[4][2];
            const int kk = ks * 8 + (lane & 3);
            #pragma unroll
            for (int s = 0; s < 2; s++) {
                int rr = wm * 32 + s * 16 + (lane >> 2);
                a[s][0] = As[rr][kk];
                a[s][1] = As[rr + 8][kk];
                a[s][2] = As[rr][kk + 4];
                a[s][3] = As[rr + 8][kk + 4];
            }
            #pragma unroll
            for (int u = 0; u < 4; u++) {
                int cc = wn * 32 + u * 8 + (lane >> 2);
                bb[u][0] = Bs[kk][cc];
                bb[u][1] = Bs[kk + 4][cc];
            }
            #pragma unroll
            for (int s = 0; s < 2; s++)
                #pragma unroll
                for (int u = 0; u < 4; u++)
                    mma8(acc[s][u], a[s], bb[u]);
        }
        __syncthreads();
    }

    #pragma unroll
    for (int s = 0; s < 2; s++) {
        int row = m0 + wm * 32 + s * 16 + (lane >> 2);
        #pragma unroll
        for (int u = 0; u < 4; u++) {
            int col = n0 + wn * 32 + u * 8 + 2 * (lane & 3);
            size_t base = (size_t)row * 2048 + col;
            g_pre[base]                      = acc[s][u][0] + g_bp[col];
            g_pre[base + 1]                  = acc[s][u][1] + g_bp[col + 1];
            g_pre[base + (size_t)8*2048]     = acc[s][u][2] + g_bp[col];
            g_pre[base + (size_t)8*2048 + 1] = acc[s][u][3] + g_bp[col + 1];
        }
    }
}

// ---------------------------------------------------------------------------
// Kernel 2: init — reset barrier counter, publish tf32-rounded initial h.
// ---------------------------------------------------------------------------
__global__ void init_state_kernel(const float* __restrict__ ih) {
    int i = blockIdx.x * 256 + threadIdx.x;
    if (i == 0) g_cnt = 0u;
    if (i < BB * HH) g_h[0][i] = __uint_as_float(f2tf32(ih[i]));
}

// ---------------------------------------------------------------------------
// Kernel 3: persistent LSTM recurrence. 128 CTAs, one per (batch-quarter,
// 64-col' chunk). Wh slice resident in SMEM for all 512 steps; c and h of
// the owned outputs live in registers; h broadcast via ping-pong global
// buffers + software grid barrier.
// ---------------------------------------------------------------------------
__global__ void __launch_bounds__(256, 1) lstm_persist_kernel(
    const int* __restrict__ nwords, const float* __restrict__ ic,
    const float* __restrict__ ih,
    float* __restrict__ out, float* __restrict__ c_final, float* __restrict__ h_final)
{
    extern __shared__ unsigned char smraw[];
    uint32_t (*As)[ASTRIDE] = (uint32_t(*)[ASTRIDE])smraw;                       // 32 x 524
    uint32_t (*Bt)[BSTRIDE] = (uint32_t(*)[BSTRIDE])(smraw + ROWS*ASTRIDE*4);    // 64 x 524 (B^T)
    float    (*zs)[ZSTRIDE] = (float(*)[ZSTRIDE])(smraw + ROWS*ASTRIDE*4 + NC*BSTRIDE*4);

    const int tid  = threadIdx.x;
    const int lane = tid & 31;
    const int warp = tid >> 5;
    const int rb = blockIdx.x & 3;        // batch quarter
    const int cn = blockIdx.x >> 2;       // 0..31 col' chunk
    const int n0 = cn * NC;               // col' base

    // --- load Wh slice into SMEM transposed: Bt[cc][k], tf32 ---
    #pragma unroll 4
    for (int j = 0; j < (NC * 512) / 256; j++) {
        int idx = tid + 256 * j;
        int cc = idx & (NC - 1);
        int k  = idx >> 6;
        Bt[cc][k] = f2tf32(g_Whp[(size_t)k * 2048 + n0 + cc]);
    }

    // --- epilogue thread mapping: thread owns (gb, hc0) and (gb, hc0+1) ---
    const int r_ep = tid >> 3;                 // 0..31 local batch row
    const int hl2  = (tid & 7) * 2;            // local h col pair base (0..14)
    const int gb   = rb * ROWS + r_ep;         // global batch row
    const int hc0  = cn * 16 + hl2;            // global h col
    const int mynw = nwords[gb];
    float c0 = ic[gb * HH + hc0];
    float c1 = ic[gb * HH + hc0 + 1];
    float hr0 = ih[gb * HH + hc0];
    float hr1 = ih[gb * HH + hc0 + 1];

    // --- MMA thread mapping: 8 warps as 2 (m16) x 4 (n16) ---
    const int wm = warp >> 2;
    const int wn = warp & 3;
    const int r0 = wm * 16 + (lane >> 2);
    const int cB0 = wn * 16 + (lane >> 2);
    const int kl = lane & 3;

    // --- A-fill mapping ---
    const int fr = tid >> 3;                   // row 0..31
    const int fc = tid & 7;                    // float4 group

    __syncthreads();                           // Bt ready

    for (int t = 0; t < TT; t++) {
        const float* __restrict__ h_in  = g_h[t & 1];
        float*       __restrict__ h_out = g_h[(t & 1) ^ 1];

        // prefetch pre-activations for the owned outputs (streaming)
        size_t pbase = ((size_t)gb * TT + t) * 2048 + n0 + hl2 * 4;
        float4 p0 = __ldcs((const float4*)(g_pre + pbase));
        float4 p1 = __ldcs((const float4*)(g_pre + pbase + 4));

        // fill As with this CTA's 32 h rows (L2-coherent loads, raw copy —
        // values were tf32-rounded at write time)
        {
            const float4* src = (const float4*)(h_in + (size_t)(rb * ROWS + fr) * HH) + fc;
            #pragma unroll
            for (int j = 0; j < 16; j++) {
                float4 v = __ldcg(src + 8 * j);
                *(float4*)&As[fr][(fc + 8 * j) * 4] = v;
            }
        }
        __syncthreads();

        // GEMM: [32 x 512] @ [512 x 64], all operands in SMEM
        float acc0[4] = {0.f, 0.f, 0.f, 0.f};
        float acc1[4] = {0.f, 0.f, 0.f, 0.f};
        #pragma unroll 8
        for (int ks = 0; ks < 64; ks++) {
            const int kk = ks * 8 + kl;
            uint32_t a[4], b0[2], b1[2];
            a[0] = As[r0][kk];     a[1] = As[r0 + 8][kk];
            a[2] = As[r0][kk + 4]; a[3] = As[r0 + 8][kk + 4];
            b0[0] = Bt[cB0][kk];     b0[1] = Bt[cB0][kk + 4];
            b1[0] = Bt[cB0 + 8][kk]; b1[1] = Bt[cB0 + 8][kk + 4];
            mma8(acc0, a, b0);
            mma8(acc1, a, b1);
        }

        // stage z tile to SMEM for the epilogue remap
        {
            int zr  = wm * 16 + (lane >> 2);
            int zc0 = wn * 16 + 2 * (lane & 3);
            zs[zr][zc0]         = acc0[0]; zs[zr][zc0 + 1]     = acc0[1];
            zs[zr + 8][zc0]     = acc0[2]; zs[zr + 8][zc0 + 1] = acc0[3];
            zs[zr][zc0 + 8]     = acc1[0]; zs[zr][zc0 + 9]     = acc1[1];
            zs[zr + 8][zc0 + 8] = acc1[2]; zs[zr + 8][zc0 + 9] = acc1[3];
        }
        __syncthreads();

        // fused gate epilogue for the 2 owned h columns
        float4 z0 = *(const float4*)&zs[r_ep][4 * hl2];
        float4 z1 = *(const float4*)&zs[r_ep][4 * hl2 + 4];
        float zi0 = z0.x + p0.x, zj0 = z0.y + p0.y, zf0 = z0.z + p0.z, zo0 = z0.w + p0.w;
        float zi1 = z1.x + p1.x, zj1 = z1.y + p1.y, zf1 = z1.z + p1.z, zo1 = z1.w + p1.w;

        float si0 = 1.f / (1.f + __expf(-zi0));
        float sf0 = 1.f / (1.f + __expf(-(zf0 + 1.0f)));
        float so0 = 1.f / (1.f + __expf(-zo0));
        float tj0 = tanhf(zj0);
        float nc0 = c0 * sf0 + si0 * tj0;
        float nh0 = tanhf(nc0) * so0;

        float si1 = 1.f / (1.f + __expf(-zi1));
        float sf1 = 1.f / (1.f + __expf(-(zf1 + 1.0f)));
        float so1 = 1.f / (1.f + __expf(-zo1));
        float tj1 = tanhf(zj1);
        float nc1 = c1 * sf1 + si1 * tj1;
        float nh1 = tanhf(nc1) * so1;

        bool m = t < mynw;
        c0 = m ? nc0 : c0;   c1 = m ? nc1 : c1;
        hr0 = m ? nh0 : hr0; hr1 = m ? nh1 : hr1;

        size_t sidx = (size_t)gb * HH + hc0;
        h_out[sidx]     = __uint_as_float(f2tf32(hr0));
        h_out[sidx + 1] = __uint_as_float(f2tf32(hr1));
        out[(size_t)t * (BB * HH) + sidx]     = m ? nh0 : 0.f;
        out[(size_t)t * (BB * HH) + sidx + 1] = m ? nh1 : 0.f;

        // grid barrier (not needed after the last step)
        if (t != TT - 1) {
            __threadfence();
            __syncthreads();
            if (tid == 0) {
                atomicAdd(&g_cnt, 1u);
                unsigned target = (unsigned)NCTA * (unsigned)(t + 1);
                while (*(volatile unsigned*)&g_cnt < target) { }
            }
            __syncthreads();
        }
    }

    // final states (each (b,h) owned by exactly one thread)
    size_t sidx = (size_t)gb * HH + hc0;
    c_final[sidx]     = c0;  c_final[sidx + 1] = c1;
    h_final[sidx]     = hr0; h_final[sidx + 1] = hr1;
}

// ---------------------------------------------------------------------------
extern "C" void kernel_launch(void* const* d_in, const int* in_sizes, int n_in,
                              void* d_out, int out_size) {
    const float* x    = (const float*)d_in[0];  // [B,T,D]
    const int*   nw   = (const int*)  d_in[1];  // [B]
    const float* ic   = (const float*)d_in[2];  // [B,H]
    const float* ih   = (const float*)d_in[3];  // [B,H]
    const float* W    = (const float*)d_in[4];  // [D+H, 4H]
    const float* bias = (const float*)d_in[5];  // [4H]

    float* out     = (float*)d_out;
    float* c_final = out + (size_t)TT * BB * HH;
    float* h_final = c_final + (size_t)BB * HH;

    const int smem_bytes = ROWS * ASTRIDE * 4 + NC * BSTRIDE * 4 + ROWS * ZSTRIDE * 4;
    cudaFuncSetAttribute(lstm_persist_kernel,
                         cudaFuncAttributeMaxDynamicSharedMemorySize, smem_bytes);

    permute_W_kernel<<<8192, 256>>>(W, bias);
    gemm_x_kernel<<<dim3(32, 512), 256>>>(x);
    init_state_kernel<<<(BB * HH + 255) / 256, 256>>>(ih);
    lstm_persist_kernel<<<NCTA, 256, smem_bytes>>>(nw, ic, ih, out, c_final, h_final);
}

// round 4
// speedup vs baseline: 3.8626x; 1.0570x over previous
#include <cuda_runtime.h>
#include <cstdint>

// Problem constants
#define BB 128
#define TT 512
#define DD 512
#define HH 512
#define G4 2048            // 4*H
#define MX (BB*TT)

// Persistent-kernel tiling
#define NCTA 128
#define ROWS 32            // batch rows per CTA (one quarter)
#define NC   64            // permuted cols per CTA (=> 16 h cols)
#define AST  516           // As word stride (516 % 32 == 4 -> conflict-free frags)
#define BST  516           // Bt word stride
#define ZST  68            // zs word stride

// Device scratch (allocation-free requirement: __device__ globals)
__device__ float g_pre[(size_t)MX * G4];     // x@Wx + b, permuted cols, row m = b*T + t
__device__ float g_Wxp[DD * G4];
__device__ float g_Whp[HH * G4];
__device__ float g_bp[G4];
__device__ float g_h[2][BB * HH];            // ping-pong hidden state (sorted batch order)
__device__ int   g_srcb[BB];                 // sorted pos -> original batch row
__device__ int   g_nws[BB];                  // num_words in sorted (descending) order
__device__ unsigned g_cnt;                   // grid barrier counter

__device__ __forceinline__ uint32_t f2tf32(float f) {
    uint32_t u;
    asm("cvt.rna.tf32.f32 %0, %1;" : "=r"(u) : "f"(f));
    return u;
}

__device__ __forceinline__ void mma8(float d[4], const uint32_t a[4], const uint32_t b[2]) {
    asm volatile(
        "mma.sync.aligned.m16n8k8.row.col.f32.tf32.tf32.f32 "
        "{%0,%1,%2,%3}, {%4,%5,%6,%7}, {%8,%9}, {%0,%1,%2,%3};"
        : "+f"(d[0]), "+f"(d[1]), "+f"(d[2]), "+f"(d[3])
        : "r"(a[0]), "r"(a[1]), "r"(a[2]), "r"(a[3]), "r"(b[0]), "r"(b[1]));
}

// ---------------------------------------------------------------------------
// Kernel 0: permute W (gate-blocked cols -> interleaved col' = 4*h + g)
// ---------------------------------------------------------------------------
__global__ void permute_W_kernel(const float* __restrict__ W, const float* __restrict__ bias) {
    int idx = blockIdx.x * 256 + threadIdx.x;
    if (idx < 1024 * 2048) {
        int d = idx >> 11;
        int col = idx & 2047;
        int g = col >> 9;
        int h = col & 511;
        int colp = 4 * h + g;
        float v = W[idx];
        if (d < 512) g_Wxp[d * 2048 + colp] = v;
        else         g_Whp[(d - 512) * 2048 + colp] = v;
    }
    if (idx < 2048) {
        int g = idx >> 9;
        int h = idx & 511;
        g_bp[4 * h + g] = bias[idx];
    }
}

// ---------------------------------------------------------------------------
// Kernel 1: input projection GEMM  g_pre = X @ Wxp + b   (X viewed [65536 x 512])
// ---------------------------------------------------------------------------
__global__ void __launch_bounds__(256) gemm_x_kernel(const float* __restrict__ X) {
    __shared__ uint32_t As[128][33];
    __shared__ uint32_t Bs[32][65];
    const int n0 = blockIdx.x * 64;
    const int m0 = blockIdx.y * 128;
    const int tid = threadIdx.x;
    const int lane = tid & 31;
    const int warp = tid >> 5;
    const int wm = warp >> 1, wn = warp & 1;

    float acc[2][4][4];
    #pragma unroll
    for (int s = 0; s < 2; s++)
        #pragma unroll
        for (int u = 0; u < 4; u++)
            #pragma unroll
            for (int i = 0; i < 4; i++) acc[s][u][i] = 0.f;

    for (int k0 = 0; k0 < 512; k0 += 32) {
        {
            int r = tid >> 1;
            int c = (tid & 1) * 16;
            const float* srcA = X + (size_t)(m0 + r) * 512 + k0 + c;
            #pragma unroll
            for (int i = 0; i < 4; i++) {
                float4 v = *(const float4*)(srcA + 4 * i);
                As[r][c + 4*i + 0] = f2tf32(v.x);
                As[r][c + 4*i + 1] = f2tf32(v.y);
                As[r][c + 4*i + 2] = f2tf32(v.z);
                As[r][c + 4*i + 3] = f2tf32(v.w);
            }
        }
        {
            int r = tid >> 3;
            int c = (tid & 7) * 8;
            const float* srcB = g_Wxp + (size_t)(k0 + r) * 2048 + n0 + c;
            #pragma unroll
            for (int i = 0; i < 2; i++) {
                float4 v = *(const float4*)(srcB + 4 * i);
                Bs[r][c + 4*i + 0] = f2tf32(v.x);
                Bs[r][c + 4*i + 1] = f2tf32(v.y);
                Bs[r][c + 4*i + 2] = f2tf32(v.z);
                Bs[r][c + 4*i + 3] = f2tf32(v.w);
            }
        }
        __syncthreads();

        #pragma unroll
        for (int ks = 0; ks < 4; ks++) {
            uint32_t a[2][4], bb[4][2];
            const int kk = ks * 8 + (lane & 3);
            #pragma unroll
            for (int s = 0; s < 2; s++) {
                int rr = wm * 32 + s * 16 + (lane >> 2);
                a[s][0] = As[rr][kk];
                a[s][1] = As[rr + 8][kk];
                a[s][2] = As[rr][kk + 4];
                a[s][3] = As[rr + 8][kk + 4];
            }
            #pragma unroll
            for (int u = 0; u < 4; u++) {
                int cc = wn * 32 + u * 8 + (lane >> 2);
                bb[u][0] = Bs[kk][cc];
                bb[u][1] = Bs[kk + 4][cc];
            }
            #pragma unroll
            for (int s = 0; s < 2; s++)
                #pragma unroll
                for (int u = 0; u < 4; u++)
                    mma8(acc[s][u], a[s], bb[u]);
        }
        __syncthreads();
    }

    #pragma unroll
    for (int s = 0; s < 2; s++) {
        int row = m0 + wm * 32 + s * 16 + (lane >> 2);
        #pragma unroll
        for (int u = 0; u < 4; u++) {
            int col = n0 + wn * 32 + u * 8 + 2 * (lane & 3);
            size_t base = (size_t)row * 2048 + col;
            g_pre[base]                      = acc[s][u][0] + g_bp[col];
            g_pre[base + 1]                  = acc[s][u][1] + g_bp[col + 1];
            g_pre[base + (size_t)8*2048]     = acc[s][u][2] + g_bp[col];
            g_pre[base + (size_t)8*2048 + 1] = acc[s][u][3] + g_bp[col + 1];
        }
    }
}

// ---------------------------------------------------------------------------
// Kernel 2a: sort batch rows by num_words descending (stable).
// ---------------------------------------------------------------------------
__global__ void sort_kernel(const int* __restrict__ nw) {
    int b = threadIdx.x;
    if (b < BB) {
        int my = nw[b];
        int rank = 0;
        for (int j = 0; j < BB; j++) {
            int v = nw[j];
            rank += (v > my) || (v == my && j < b);
        }
        g_srcb[rank] = b;
        g_nws[rank] = my;
    }
}

// ---------------------------------------------------------------------------
// Kernel 2b: init — reset barrier counter, publish tf32-rounded initial h
// in sorted batch order.
// ---------------------------------------------------------------------------
__global__ void init_state_kernel(const float* __restrict__ ih) {
    int i = blockIdx.x * 256 + threadIdx.x;
    if (i == 0) g_cnt = 0u;
    if (i < BB * HH) {
        int srow = i >> 9;
        int col = i & 511;
        int borig = g_srcb[srow];
        g_h[0][i] = __uint_as_float(f2tf32(ih[borig * HH + col]));
    }
}

// ---------------------------------------------------------------------------
// Kernel 3: persistent LSTM recurrence.
// 128 CTAs = 4 batch quarters (sorted) x 32 col' chunks of 64.
// GEMM: 8 warps = 2 n-halves x 4 K-slices; warp tile 32m x 32n over K=128,
// partials reduced through SMEM (zs overlaid on the As buffer).
// Quarters whose rows are all inactive at step t skip the GEMM entirely.
// ---------------------------------------------------------------------------
__global__ void __launch_bounds__(256, 1) lstm_persist_kernel(
    const float* __restrict__ ic, const float* __restrict__ ih,
    float* __restrict__ out, float* __restrict__ c_final, float* __restrict__ h_final)
{
    extern __shared__ unsigned char smraw[];
    uint32_t* As = (uint32_t*)smraw;                       // [32][AST] words
    float*    zs = (float*)smraw;                          // [4][32][ZST] overlay on As
    uint32_t* Bt = (uint32_t*)(smraw + ROWS * AST * 4);    // [64][BST] words (B^T)

    const int tid  = threadIdx.x;
    const int lane = tid & 31;
    const int warp = tid >> 5;
    const int rb = blockIdx.x & 3;        // batch quarter (sorted order)
    const int cn = blockIdx.x >> 2;       // 0..31 col' chunk
    const int n0 = cn * NC;               // col' base

    // --- load Wh slice into SMEM transposed: Bt[cc][k], tf32 ---
    #pragma unroll 4
    for (int j = 0; j < (NC * 512) / 256; j++) {
        int idx = tid + 256 * j;
        int cc = idx & (NC - 1);
        int k  = idx >> 6;
        Bt[cc * BST + k] = f2tf32(g_Whp[(size_t)k * 2048 + n0 + cc]);
    }

    // --- epilogue mapping: thread owns (srow, hc0) and (srow, hc0+1) ---
    const int r_ep = tid & 31;                 // local batch row (== lane)
    const int hl2  = (tid >> 5) * 2;           // local h col pair (0,2,..,14)
    const int srow = rb * ROWS + r_ep;         // sorted batch row
    const int borig = g_srcb[srow];            // original batch row
    const int mynw  = g_nws[srow];
    const int qmax  = g_nws[rb * ROWS];        // max num_words in this quarter
    float c0  = ic[borig * HH + cn * 16 + hl2];
    float c1  = ic[borig * HH + cn * 16 + hl2 + 1];
    float hr0 = ih[borig * HH + cn * 16 + hl2];
    float hr1 = ih[borig * HH + cn * 16 + hl2 + 1];
    const size_t outcol = (size_t)borig * HH + cn * 16 + hl2;

    // --- MMA mapping: 8 warps = 2 n-halves x 4 K-slices; warp tile 32x32 ---
    const int wn = warp & 1;
    const int kw = warp >> 1;
    const int kbase = kw * 128;
    const int ln4 = lane >> 2;
    const int kl  = lane & 3;

    // --- A-fill mapping ---
    const int fr = tid >> 3;                   // row 0..31
    const int fc = tid & 7;                    // float4 group

    __syncthreads();                           // Bt ready

    for (int t = 0; t < TT; t++) {
        if (t < qmax) {
            const float* __restrict__ h_in  = g_h[t & 1];
            float*       __restrict__ h_out = g_h[(t & 1) ^ 1];

            // prefetch pre-activations for the owned outputs (streaming)
            size_t pbase = ((size_t)borig * TT + t) * 2048 + n0 + hl2 * 4;
            float4 p0 = __ldcs((const float4*)(g_pre + pbase));
            float4 p1 = __ldcs((const float4*)(g_pre + pbase + 4));

            // fill As with this quarter's 32 h rows (L2-coherent, raw copy)
            {
                const float4* src = (const float4*)(h_in + (size_t)(rb * ROWS + fr) * HH) + fc;
                #pragma unroll
                for (int j = 0; j < 16; j++) {
                    float4 v = __ldcg(src + 8 * j);
                    *(float4*)&As[fr * AST + (fc + 8 * j) * 4] = v;
                }
            }
            __syncthreads();

            // GEMM: [32 x 128] @ [128 x 32] per warp (K slice kw, n half wn)
            float acc[2][4][4];
            #pragma unroll
            for (int s = 0; s < 2; s++)
                #pragma unroll
                for (int u = 0; u < 4; u++)
                    #pragma unroll
                    for (int i = 0; i < 4; i++) acc[s][u][i] = 0.f;

            #pragma unroll 8
            for (int ks = 0; ks < 16; ks++) {
                const int kk = kbase + ks * 8 + kl;
                uint32_t a[2][4], bb[4][2];
                #pragma unroll
                for (int s = 0; s < 2; s++) {
                    int rr = s * 16 + ln4;
                    a[s][0] = As[rr * AST + kk];
                    a[s][1] = As[(rr + 8) * AST + kk];
                    a[s][2] = As[rr * AST + kk + 4];
                    a[s][3] = As[(rr + 8) * AST + kk + 4];
                }
                #pragma unroll
                for (int u = 0; u < 4; u++) {
                    int cc = wn * 32 + u * 8 + ln4;
                    bb[u][0] = Bt[cc * BST + kk];
                    bb[u][1] = Bt[cc * BST + kk + 4];
                }
                #pragma unroll
                for (int s = 0; s < 2; s++)
                    #pragma unroll
                    for (int u = 0; u < 4; u++)
                        mma8(acc[s][u], a[s], bb[u]);
            }
            __syncthreads();   // all As reads done before zs overlay writes

            // store partials: zs[kw][row][col]
            {
                int zcb = wn * 32 + 2 * kl;
                #pragma unroll
                for (int s = 0; s < 2; s++) {
                    int row = s * 16 + ln4;
                    #pragma unroll
                    for (int u = 0; u < 4; u++) {
                        int col = zcb + u * 8;
                        *(float2*)&zs[(kw * 32 + row) * ZST + col]     =
                            make_float2(acc[s][u][0], acc[s][u][1]);
                        *(float2*)&zs[(kw * 32 + row + 8) * ZST + col] =
                            make_float2(acc[s][u][2], acc[s][u][3]);
                    }
                }
            }
            __syncthreads();

            // reduce 4 K-partials + fused gate epilogue (2 owned h cols)
            float4 z0 = make_float4(0.f, 0.f, 0.f, 0.f);
            float4 z1 = make_float4(0.f, 0.f, 0.f, 0.f);
            #pragma unroll
            for (int s = 0; s < 4; s++) {
                const float* zp = zs + ((s * 32 + r_ep) * ZST + hl2 * 4);
                float4 a0 = *(const float4*)zp;
                float4 a1 = *(const float4*)(zp + 4);
                z0.x += a0.x; z0.y += a0.y; z0.z += a0.z; z0.w += a0.w;
                z1.x += a1.x; z1.y += a1.y; z1.z += a1.z; z1.w += a1.w;
            }

            float zi0 = z0.x + p0.x, zj0 = z0.y + p0.y, zf0 = z0.z + p0.z, zo0 = z0.w + p0.w;
            float zi1 = z1.x + p1.x, zj1 = z1.y + p1.y, zf1 = z1.z + p1.z, zo1 = z1.w + p1.w;

            float si0 = 1.f / (1.f + __expf(-zi0));
            float sf0 = 1.f / (1.f + __expf(-(zf0 + 1.0f)));
            float so0 = 1.f / (1.f + __expf(-zo0));
            float tj0 = tanhf(zj0);
            float nc0 = c0 * sf0 + si0 * tj0;
            float nh0 = tanhf(nc0) * so0;

            float si1 = 1.f / (1.f + __expf(-zi1));
            float sf1 = 1.f / (1.f + __expf(-(zf1 + 1.0f)));
            float so1 = 1.f / (1.f + __expf(-zo1));
            float tj1 = tanhf(zj1);
            float nc1 = c1 * sf1 + si1 * tj1;
            float nh1 = tanhf(nc1) * so1;

            bool m = t < mynw;
            c0 = m ? nc0 : c0;   c1 = m ? nc1 : c1;
            hr0 = m ? nh0 : hr0; hr1 = m ? nh1 : hr1;

            size_t sidx = (size_t)srow * HH + cn * 16 + hl2;
            *(float2*)&h_out[sidx] = make_float2(__uint_as_float(f2tf32(hr0)),
                                                 __uint_as_float(f2tf32(hr1)));
            *(float2*)&out[(size_t)t * (BB * HH) + outcol] =
                make_float2(m ? nh0 : 0.f, m ? nh1 : 0.f);
        } else {
            // quarter fully inactive: outputs are zeros, state frozen in regs
            *(float2*)&out[(size_t)t * (BB * HH) + outcol] = make_float2(0.f, 0.f);
        }

        // grid barrier (not needed after the last step)
        if (t != TT - 1) {
            __threadfence();
            __syncthreads();
            if (tid == 0) {
                atomicAdd(&g_cnt, 1u);
                unsigned target = (unsigned)NCTA * (unsigned)(t + 1);
                while (*(volatile unsigned*)&g_cnt < target) { }
            }
            __syncthreads();
        }
    }

    // final states (each (b,h) pair owned by exactly one thread)
    *(float2*)&c_final[outcol] = make_float2(c0, c1);
    *(float2*)&h_final[outcol] = make_float2(hr0, hr1);
}

// ---------------------------------------------------------------------------
extern "C" void kernel_launch(void* const* d_in, const int* in_sizes, int n_in,
                              void* d_out, int out_size) {
    const float* x    = (const float*)d_in[0];  // [B,T,D]
    const int*   nw   = (const int*)  d_in[1];  // [B]
    const float* ic   = (const float*)d_in[2];  // [B,H]
    const float* ih   = (const float*)d_in[3];  // [B,H]
    const float* W    = (const float*)d_in[4];  // [D+H, 4H]
    const float* bias = (const float*)d_in[5];  // [4H]

    float* out     = (float*)d_out;
    float* c_final = out + (size_t)TT * BB * HH;
    float* h_final = c_final + (size_t)BB * HH;

    const int smem_bytes = ROWS * AST * 4 + NC * BST * 4;   // 198144
    cudaFuncSetAttribute(lstm_persist_kernel,
                         cudaFuncAttributeMaxDynamicSharedMemorySize, smem_bytes);

    permute_W_kernel<<<8192, 256>>>(W, bias);
    gemm_x_kernel<<<dim3(32, 512), 256>>>(x);
    sort_kernel<<<1, 128>>>(nw);
    init_state_kernel<<<(BB * HH + 255) / 256, 256>>>(ih);
    lstm_persist_kernel<<<NCTA, 256, smem_bytes>>>(ic, ih, out, c_final, h_final);
}